// round 9
// baseline (speedup 1.0000x reference)
#include <cuda_runtime.h>

#define NN 50000
#define EE 800000
#define TT 3
#define HH 8
#define D1 64
#define C2 16

typedef unsigned long long u64;

// ---------------- scratch (static device globals; no allocation) ----------------
__device__ float g_feat1[NN * TT * D1];   // 38.4 MB
__device__ float g_es1[NN * TT * HH];     // 4.8 MB  [n][t][h]
__device__ float g_h[NN * D1];            // 12.8 MB
__device__ float g_feat2[NN * TT * C2];   // 9.6 MB
__device__ float g_es2[NN * TT];          // 0.6 MB
__device__ float g_resid[NN * C2];        // 3.2 MB
__device__ float g_v1[D1 * TT * HH];
__device__ float g_v2[TT * D1];
__device__ float g_Wc[D1 * 64];
__device__ int   g_deg[NN];
__device__ int   g_rowptr[NN + 1];
__device__ int   g_cursor[NN];
__device__ int   g_gather[EE];

#define HIST_BLOCKS ((EE + 1023) / 1024)

#define PAD 68
#define GEMM_SMEM ((128 + 64) * PAD * 4)   // xs[128][68] + wst[64][68] = 52224 B

__device__ __forceinline__ void ffma2(u64& d, u64 a, u64 b) {
    asm("fma.rn.f32x2 %0, %1, %2, %0;" : "+l"(d) : "l"(a), "l"(b));
}
__device__ __forceinline__ float unpack_sum(u64 v) {
    float2 f = *reinterpret_cast<float2*>(&v);
    return f.x + f.y;
}

// 8x4 micro-tile, k-packed f32x2, B transposed in smem. acc[i][c] holds (even-k, odd-k) sums.
#define GEMM_CORE_T(XS, WST, ACC, RR, CC)                                           \
    _Pragma("unroll")                                                               \
    for (int k4 = 0; k4 < 64; k4 += 4) {                                            \
        ulonglong2 b0 = *reinterpret_cast<const ulonglong2*>(&WST[CC][k4]);         \
        ulonglong2 b1 = *reinterpret_cast<const ulonglong2*>(&WST[CC + 1][k4]);     \
        ulonglong2 b2 = *reinterpret_cast<const ulonglong2*>(&WST[CC + 2][k4]);     \
        ulonglong2 b3 = *reinterpret_cast<const ulonglong2*>(&WST[CC + 3][k4]);     \
        _Pragma("unroll")                                                           \
        for (int i = 0; i < 8; i++) {                                               \
            ulonglong2 a = *reinterpret_cast<const ulonglong2*>(&XS[RR + i][k4]);   \
            ffma2(ACC[i][0], a.x, b0.x); ffma2(ACC[i][0], a.y, b0.y);               \
            ffma2(ACC[i][1], a.x, b1.x); ffma2(ACC[i][1], a.y, b1.y);               \
            ffma2(ACC[i][2], a.x, b2.x); ffma2(ACC[i][2], a.y, b2.y);               \
            ffma2(ACC[i][3], a.x, b3.x); ffma2(ACC[i][3], a.y, b3.y);               \
        }                                                                           \
    }

// ---------------- setup: hist + zero d_out + build v1/v2/Wc ----------------
__global__ void k_setup(const float* __restrict__ al1, const float* __restrict__ ar1,
                        const float* __restrict__ al2, const float* __restrict__ ar2,
                        const float* __restrict__ W1, const float* __restrict__ W2,
                        const float* __restrict__ res_w, const int* __restrict__ dst,
                        float* __restrict__ d_out) {
    int b = blockIdx.x;
    int tid = threadIdx.x;
    if (b < HIST_BLOCKS) {
        int t0 = b * 1024 + tid;
#pragma unroll
        for (int k = 0; k < 4; k++) {
            int e = t0 + k * 256;
            if (e < EE) atomicAdd(&g_deg[dst[e]], 1);
        }
        return;
    }
    b -= HIST_BLOCKS;
    if (b < TT) {
        int t = b;
        __shared__ float u1s[64][8];
        for (int e = tid; e < 512; e += 256) {
            int c = e >> 3, h = e & 7;
            const float* pl = al1 + t * 4096 + c * 64 + h * 8;
            const float* pr = ar1 + t * 4096 + c * 64 + h * 8;
            float s = 0.f;
#pragma unroll
            for (int d = 0; d < 8; d++) s += pl[d] + pr[d];
            u1s[c][h] = s;
        }
        __syncthreads();
        for (int e = tid; e < 512; e += 256) {
            int i = e >> 3, h = e & 7;
            const float* w = W1 + t * 4096 + i * 64;
            float s = 0.f;
#pragma unroll 8
            for (int c = 0; c < 64; c++) s = fmaf(w[c], u1s[c][h], s);
            g_v1[i * 24 + t * 8 + h] = s;
        }
        return;
    }
    b -= TT;
    if (b < 1) {
        __shared__ float u2s[48];
        if (tid < 48) {
            int t = tid >> 4, c = tid & 15;
            const float* pl = al2 + (t * 16 + c) * 16;
            const float* pr = ar2 + (t * 16 + c) * 16;
            float s = 0.f;
#pragma unroll
            for (int j = 0; j < 16; j++) s += pl[j] + pr[j];
            u2s[tid] = s;
        }
        if (tid >= 240 && tid < 240 + C2) d_out[tid - 240] = 0.f;
        __syncthreads();
        if (tid < 192) {
            int t = tid >> 6, i = tid & 63;
            const float* w = W2 + (t * 64 + i) * 16;
            float s = 0.f;
#pragma unroll
            for (int c = 0; c < 16; c++) s = fmaf(w[c], u2s[t * 16 + c], s);
            g_v2[tid] = s;
        }
        return;
    }
    b -= 1;
    if (b < 16) {
        int i = b * 256 + tid;
        int k = i >> 6, c = i & 63;
        float v;
        if (c < 48) v = W2[(((c >> 4) * D1) + k) * C2 + (c & 15)];
        else        v = res_w[k * C2 + (c - 48)];
        g_Wc[i] = v;
        return;
    }
}

// ---------------- scan ----------------
__global__ void k_scan() {
    extern __shared__ int sdeg[];
    __shared__ int ss[1024];
    int tid = threadIdx.x;
    for (int i = tid; i < NN; i += 1024) sdeg[i] = g_deg[i];
    __syncthreads();
    const int CH = 49;
    int base = tid * CH;
    int s = 0;
    for (int i = 0; i < CH; i++) {
        int j = base + i;
        if (j < NN) s += sdeg[j];
    }
    ss[tid] = s;
    __syncthreads();
    for (int off = 1; off < 1024; off <<= 1) {
        int v = (tid >= off) ? ss[tid - off] : 0;
        __syncthreads();
        ss[tid] += v;
        __syncthreads();
    }
    if (tid == 1023) g_rowptr[NN] = ss[1023];
    int run = (tid > 0) ? ss[tid - 1] : 0;
    for (int i = 0; i < CH; i++) {
        int j = base + i;
        if (j < NN) {
            int d = sdeg[j];
            sdeg[j] = run;
            run += d;
        }
    }
    __syncthreads();
    for (int i = tid; i < NN; i += 1024) {
        int v = sdeg[i];
        g_rowptr[i] = v;
        g_cursor[i] = v;
    }
}

// ---------------- scatter ----------------
__global__ void k_scatter(const int* __restrict__ src, const int* __restrict__ dst,
                          const int* __restrict__ etype) {
    int t0 = blockIdx.x * 1024 + threadIdx.x;
#pragma unroll
    for (int k = 0; k < 4; k++) {
        int e = t0 + k * 256;
        if (e < EE) {
            int pos = atomicAdd(&g_cursor[dst[e]], 1);
            g_gather[pos] = src[e] * TT + etype[e];
        }
    }
    int gt = blockIdx.x * 256 + threadIdx.x;
    for (int i = gt; i < NN; i += gridDim.x * 256) g_deg[i] = 0;
}

// ---------------- layer0: y<3 -> feat1 GEMM (128-row tile); y==3 -> es1 ----------------
__global__ void __launch_bounds__(256) k_l1(const float* __restrict__ x,
                                            const float* __restrict__ W1) {
    extern __shared__ float sm[];
    float (*xs)[PAD] = reinterpret_cast<float(*)[PAD]>(sm);            // [128][68]
    float (*wst)[PAD] = reinterpret_cast<float(*)[PAD]>(sm + 128 * PAD); // [64][68]
    int r0 = blockIdx.x * 128;
    int tid = threadIdx.x;
    // load x tile: 128 rows x 64 k
    for (int i = tid; i < 128 * 16; i += 256) {
        int r = i >> 4, c4 = (i & 15) << 2;
        float4 v = make_float4(0.f, 0.f, 0.f, 0.f);
        if (r0 + r < NN) v = *reinterpret_cast<const float4*>(x + (r0 + r) * 64 + c4);
        *reinterpret_cast<float4*>(&xs[r][c4]) = v;
    }
    if (blockIdx.y < 3) {
        int t = blockIdx.y;
        // load W1[t] transposed: wst[c][k] = W1[t][k][c]
        for (int i = tid; i < 64 * 64; i += 256) {
            int k = i >> 6, c = i & 63;
            wst[c][k] = W1[t * 4096 + i];
        }
        __syncthreads();
        int cc = (tid & 15) << 2;
        int rr = (tid >> 4) << 3;
        u64 acc[8][4] = {};
        GEMM_CORE_T(xs, wst, acc, rr, cc)
#pragma unroll
        for (int i2 = 0; i2 < 8; i2++) {
            int r = r0 + rr + i2;
            if (r < NN) {
                float4 o = make_float4(unpack_sum(acc[i2][0]), unpack_sum(acc[i2][1]),
                                       unpack_sum(acc[i2][2]), unpack_sum(acc[i2][3]));
                *reinterpret_cast<float4*>(&g_feat1[(r * TT + t) * 64 + cc]) = o;
            }
        }
    } else {
        // es1[n][t*8+h] = exp(leakyrelu( x[n,:] . v1[:, t*8+h] )); 128 rows, 2 threads/row
        for (int i2 = tid; i2 < 64 * 24; i2 += 256) {
            int r = i2 / 24, c = i2 - r * 24;
            wst[r][c] = g_v1[i2];
        }
        __syncthreads();
        int row = tid >> 1;
        int c0 = (tid & 1) * 12;
        float s[12] = {};
#pragma unroll
        for (int i4 = 0; i4 < 64; i4 += 4) {
            float4 xv = *reinterpret_cast<const float4*>(&xs[row][i4]);
#pragma unroll
            for (int c = 0; c < 12; c++) {
                s[c] = fmaf(xv.x, wst[i4][c0 + c], s[c]);
                s[c] = fmaf(xv.y, wst[i4 + 1][c0 + c], s[c]);
                s[c] = fmaf(xv.z, wst[i4 + 2][c0 + c], s[c]);
                s[c] = fmaf(xv.w, wst[i4 + 3][c0 + c], s[c]);
            }
        }
        int n = r0 + row;
        if (n < NN) {
#pragma unroll
            for (int c = 0; c < 12; c++) {
                float a = s[c];
                a = a > 0.f ? a : 0.2f * a;
                g_es1[n * 24 + c0 + c] = expf(a);
            }
        }
    }
}

// ---------------- layer0 aggregation: warp-per-node, float2 lanes ----------------
__global__ void __launch_bounds__(256) k_agg1() {
    __shared__ float v2s[3][64];
    int tid = threadIdx.x;
    if (tid < 192) v2s[tid >> 6][tid & 63] = g_v2[tid];
    __syncthreads();
    int warp = tid >> 5, lane = tid & 31;
    int node = blockIdx.x * 8 + warp;
    if (node >= NN) return;
    int beg = g_rowptr[node], end = g_rowptr[node + 1];
    int j2 = lane * 2;
    int h = lane >> 2;
    float ax = 0.f, ay = 0.f, wsum = 0.f;
    int p = beg;
    for (; p + 4 <= end; p += 4) {
        int g0 = __ldg(&g_gather[p]);
        int g1 = __ldg(&g_gather[p + 1]);
        int g2 = __ldg(&g_gather[p + 2]);
        int g3 = __ldg(&g_gather[p + 3]);
        float w0 = __ldg(&g_es1[g0 * 8 + h]);
        float w1 = __ldg(&g_es1[g1 * 8 + h]);
        float w2 = __ldg(&g_es1[g2 * 8 + h]);
        float w3 = __ldg(&g_es1[g3 * 8 + h]);
        float2 f0 = __ldg(reinterpret_cast<const float2*>(&g_feat1[g0 * 64 + j2]));
        float2 f1 = __ldg(reinterpret_cast<const float2*>(&g_feat1[g1 * 64 + j2]));
        float2 f2 = __ldg(reinterpret_cast<const float2*>(&g_feat1[g2 * 64 + j2]));
        float2 f3 = __ldg(reinterpret_cast<const float2*>(&g_feat1[g3 * 64 + j2]));
        ax = fmaf(f0.x, w0, ax); ay = fmaf(f0.y, w0, ay);
        ax = fmaf(f1.x, w1, ax); ay = fmaf(f1.y, w1, ay);
        ax = fmaf(f2.x, w2, ax); ay = fmaf(f2.y, w2, ay);
        ax = fmaf(f3.x, w3, ax); ay = fmaf(f3.y, w3, ay);
        wsum += (w0 + w1) + (w2 + w3);
    }
    for (; p < end; p++) {
        int g = __ldg(&g_gather[p]);
        float w = __ldg(&g_es1[g * 8 + h]);
        float2 f = __ldg(reinterpret_cast<const float2*>(&g_feat1[g * 64 + j2]));
        ax = fmaf(f.x, w, ax); ay = fmaf(f.y, w, ay);
        wsum += w;
    }
    float vx = 0.f, vy = 0.f;
    if (end > beg) {
        vx = ax / wsum;
        vy = ay / wsum;
    }
    vx = vx > 0.f ? vx : (expf(vx) - 1.f);
    vy = vy > 0.f ? vy : (expf(vy) - 1.f);
    *reinterpret_cast<float2*>(&g_h[node * 64 + j2]) = make_float2(vx, vy);
    float p0 = vx * v2s[0][j2] + vy * v2s[0][j2 + 1];
    float p1 = vx * v2s[1][j2] + vy * v2s[1][j2 + 1];
    float p2 = vx * v2s[2][j2] + vy * v2s[2][j2 + 1];
#pragma unroll
    for (int off = 16; off > 0; off >>= 1) {
        p0 += __shfl_down_sync(0xffffffffu, p0, off);
        p1 += __shfl_down_sync(0xffffffffu, p1, off);
        p2 += __shfl_down_sync(0xffffffffu, p2, off);
    }
    if (lane == 0) {
        float s0 = p0 > 0.f ? p0 : 0.2f * p0;
        float s1 = p1 > 0.f ? p1 : 0.2f * p1;
        float s2 = p2 > 0.f ? p2 : 0.2f * p2;
        g_es2[node * 3 + 0] = expf(s0);
        g_es2[node * 3 + 1] = expf(s1);
        g_es2[node * 3 + 2] = expf(s2);
    }
}

// ---------------- layer 1 GEMM (128-row tile): [feat2 | resid] = h @ Wc ----------------
__global__ void __launch_bounds__(256) k_feat2(const float* __restrict__ res_b) {
    extern __shared__ float sm[];
    float (*xs)[PAD] = reinterpret_cast<float(*)[PAD]>(sm);
    float (*wst)[PAD] = reinterpret_cast<float(*)[PAD]>(sm + 128 * PAD);
    int r0 = blockIdx.x * 128;
    int tid = threadIdx.x;
    for (int i = tid; i < 128 * 16; i += 256) {
        int r = i >> 4, c4 = (i & 15) << 2;
        float4 v = make_float4(0.f, 0.f, 0.f, 0.f);
        if (r0 + r < NN) v = *reinterpret_cast<const float4*>(g_h + (r0 + r) * 64 + c4);
        *reinterpret_cast<float4*>(&xs[r][c4]) = v;
    }
    for (int i = tid; i < 64 * 64; i += 256) {
        int k = i >> 6, c = i & 63;
        wst[c][k] = g_Wc[i];
    }
    __syncthreads();
    int cc = (tid & 15) << 2;
    int rr = (tid >> 4) << 3;
    u64 acc[8][4] = {};
    GEMM_CORE_T(xs, wst, acc, rr, cc)
#pragma unroll
    for (int i2 = 0; i2 < 8; i2++) {
        int r = r0 + rr + i2;
        if (r < NN) {
            float o0 = unpack_sum(acc[i2][0]);
            float o1 = unpack_sum(acc[i2][1]);
            float o2 = unpack_sum(acc[i2][2]);
            float o3 = unpack_sum(acc[i2][3]);
            if (cc < 48) {
                int t = cc >> 4;
                *reinterpret_cast<float4*>(&g_feat2[(r * TT + t) * 16 + (cc & 15)]) =
                    make_float4(o0, o1, o2, o3);
            } else {
                int c0 = cc - 48;
                *reinterpret_cast<float4*>(&g_resid[r * 16 + c0]) =
                    make_float4(o0 + res_b[c0], o1 + res_b[c0 + 1],
                                o2 + res_b[c0 + 2], o3 + res_b[c0 + 3]);
            }
        }
    }
}

// ---------------- layer1 aggregation + residual + mean pooling ----------------
__global__ void __launch_bounds__(256) k_agg2(float* __restrict__ d_out) {
    __shared__ float2 red[256];
    int tid = threadIdx.x;
    int grp = tid >> 3;
    int j = tid & 7;
    int node = blockIdx.x * 32 + grp;
    float2 val = make_float2(0.f, 0.f);
    if (node < NN) {
        int beg = g_rowptr[node], end = g_rowptr[node + 1];
        float ax = 0.f, ay = 0.f, wsum = 0.f;
        int p = beg;
        for (; p + 4 <= end; p += 4) {
            int g0 = __ldg(&g_gather[p]);
            int g1 = __ldg(&g_gather[p + 1]);
            int g2 = __ldg(&g_gather[p + 2]);
            int g3 = __ldg(&g_gather[p + 3]);
            float w0 = __ldg(&g_es2[g0]);
            float w1 = __ldg(&g_es2[g1]);
            float w2 = __ldg(&g_es2[g2]);
            float w3 = __ldg(&g_es2[g3]);
            float2 f0 = __ldg(reinterpret_cast<const float2*>(&g_feat2[g0 * 16 + j * 2]));
            float2 f1 = __ldg(reinterpret_cast<const float2*>(&g_feat2[g1 * 16 + j * 2]));
            float2 f2 = __ldg(reinterpret_cast<const float2*>(&g_feat2[g2 * 16 + j * 2]));
            float2 f3 = __ldg(reinterpret_cast<const float2*>(&g_feat2[g3 * 16 + j * 2]));
            ax = fmaf(f0.x, w0, ax); ay = fmaf(f0.y, w0, ay);
            ax = fmaf(f1.x, w1, ax); ay = fmaf(f1.y, w1, ay);
            ax = fmaf(f2.x, w2, ax); ay = fmaf(f2.y, w2, ay);
            ax = fmaf(f3.x, w3, ax); ay = fmaf(f3.y, w3, ay);
            wsum += (w0 + w1) + (w2 + w3);
        }
        for (; p < end; p++) {
            int g = __ldg(&g_gather[p]);
            float w = __ldg(&g_es2[g]);
            float2 f = __ldg(reinterpret_cast<const float2*>(&g_feat2[g * 16 + j * 2]));
            ax = fmaf(f.x, w, ax); ay = fmaf(f.y, w, ay);
            wsum += w;
        }
        float2 rs = *reinterpret_cast<const float2*>(&g_resid[node * 16 + j * 2]);
        val.x = ((end > beg) ? ax / wsum : 0.f) + rs.x;
        val.y = ((end > beg) ? ay / wsum : 0.f) + rs.y;
    }
    val.x *= (1.0f / NN);
    val.y *= (1.0f / NN);
    red[tid] = val;
    __syncthreads();
#pragma unroll
    for (int s = 16; s > 0; s >>= 1) {
        if (grp < s) {
            float2 o = red[tid + s * 8];
            red[tid].x += o.x;
            red[tid].y += o.y;
        }
        __syncthreads();
    }
    if (tid < 8) {
        atomicAdd(&d_out[tid * 2], red[tid].x);
        atomicAdd(&d_out[tid * 2 + 1], red[tid].y);
    }
}

// ---------------- launch ----------------
extern "C" void kernel_launch(void* const* d_in, const int* in_sizes, int n_in,
                              void* d_out, int out_size) {
    const float* x     = (const float*)d_in[0];
    const int*   src   = (const int*)d_in[1];
    const int*   dst   = (const int*)d_in[2];
    const int*   etype = (const int*)d_in[4];
    const float* W1    = (const float*)d_in[5];
    const float* al1   = (const float*)d_in[6];
    const float* ar1   = (const float*)d_in[7];
    const float* W2    = (const float*)d_in[8];
    const float* al2   = (const float*)d_in[9];
    const float* ar2   = (const float*)d_in[10];
    const float* res_w = (const float*)d_in[11];
    const float* res_b = (const float*)d_in[12];
    float* out = (float*)d_out;

    cudaFuncSetAttribute(k_scan, cudaFuncAttributeMaxDynamicSharedMemorySize, NN * 4);
    cudaFuncSetAttribute(k_l1, cudaFuncAttributeMaxDynamicSharedMemorySize, GEMM_SMEM);
    cudaFuncSetAttribute(k_feat2, cudaFuncAttributeMaxDynamicSharedMemorySize, GEMM_SMEM);

    k_setup<<<HIST_BLOCKS + TT + 1 + 16, 256>>>(al1, ar1, al2, ar2, W1, W2, res_w, dst, out);
    k_scan<<<1, 1024, NN * 4>>>();
    k_scatter<<<HIST_BLOCKS, 256>>>(src, dst, etype);
    k_l1<<<dim3((NN + 127) / 128, 4), 256, GEMM_SMEM>>>(x, W1);
    k_agg1<<<(NN + 7) / 8, 256>>>();
    k_feat2<<<(NN + 127) / 128, 256, GEMM_SMEM>>>(res_b);
    k_agg2<<<(NN + 31) / 32, 256>>>(out);
}

// round 11
// speedup vs baseline: 1.3644x; 1.3644x over previous
#include <cuda_runtime.h>

#define NN 50000
#define EE 800000
#define TT 3
#define HH 8
#define D1 64
#define C2 16

typedef unsigned long long u64;

// ---------------- scratch (static device globals; no allocation) ----------------
__device__ float g_feat1[NN * TT * D1];   // 38.4 MB
__device__ float g_es1[NN * TT * HH];     // 4.8 MB  [n][t][h]
__device__ float g_h[NN * D1];            // 12.8 MB
__device__ float g_feat2[NN * TT * C2];   // 9.6 MB
__device__ float g_es2[NN * TT];          // 0.6 MB
__device__ float g_resid[NN * C2];        // 3.2 MB
__device__ float g_v1[D1 * TT * HH];
__device__ float g_v2[TT * D1];
__device__ float g_Wc[D1 * 64];
__device__ int   g_deg[NN];
__device__ int   g_rowptr[NN + 1];
__device__ int   g_cursor[NN];
__device__ int   g_gather[EE];

#define HIST_BLOCKS ((EE + 1023) / 1024)   // 782
#define GB ((NN + 63) / 64)                // 782 GEMM / es1 tile blocks

// ---------------- f32x2 packed-FMA helpers (round-6 proven config) ----------------
__device__ __forceinline__ u64 pack2(float v) {
    u64 r;
    unsigned u = __float_as_uint(v);
    asm("mov.b64 %0, {%1, %1};" : "=l"(r) : "r"(u));
    return r;
}
__device__ __forceinline__ void ffma2(u64& d, u64 a, u64 b) {
    asm("fma.rn.f32x2 %0, %1, %2, %0;" : "+l"(d) : "l"(a), "l"(b));
}

#define GEMM_ROW(ACCR, AV, B0, B1, B2, B3) {                                        \
        u64 t_;                                                                     \
        t_ = pack2(AV.x); ffma2(ACCR[0], t_, B0.x); ffma2(ACCR[1], t_, B0.y);       \
        t_ = pack2(AV.y); ffma2(ACCR[0], t_, B1.x); ffma2(ACCR[1], t_, B1.y);       \
        t_ = pack2(AV.z); ffma2(ACCR[0], t_, B2.x); ffma2(ACCR[1], t_, B2.y);       \
        t_ = pack2(AV.w); ffma2(ACCR[0], t_, B3.x); ffma2(ACCR[1], t_, B3.y);       \
    }

#define GEMM_CORE2(XS, WS, ACC2, RR, CC)                                            \
    _Pragma("unroll")                                                               \
    for (int k4 = 0; k4 < 64; k4 += 4) {                                            \
        float4 a0 = *reinterpret_cast<const float4*>(&XS[RR][k4]);                  \
        float4 a1 = *reinterpret_cast<const float4*>(&XS[RR + 1][k4]);              \
        float4 a2 = *reinterpret_cast<const float4*>(&XS[RR + 2][k4]);              \
        float4 a3 = *reinterpret_cast<const float4*>(&XS[RR + 3][k4]);              \
        ulonglong2 b0 = *reinterpret_cast<const ulonglong2*>(&WS[k4][CC]);          \
        ulonglong2 b1 = *reinterpret_cast<const ulonglong2*>(&WS[k4 + 1][CC]);      \
        ulonglong2 b2 = *reinterpret_cast<const ulonglong2*>(&WS[k4 + 2][CC]);      \
        ulonglong2 b3 = *reinterpret_cast<const ulonglong2*>(&WS[k4 + 3][CC]);      \
        GEMM_ROW(ACC2[0], a0, b0, b1, b2, b3)                                       \
        GEMM_ROW(ACC2[1], a1, b0, b1, b2, b3)                                       \
        GEMM_ROW(ACC2[2], a2, b0, b1, b2, b3)                                       \
        GEMM_ROW(ACC2[3], a3, b0, b1, b2, b3)                                       \
    }

// ---------------- Launch A: feat1 GEMM (fused t) + hist + v1/v2/Wc + zero d_out ----------------
__global__ void __launch_bounds__(256) k_setup(const float* __restrict__ x,
                        const float* __restrict__ al1, const float* __restrict__ ar1,
                        const float* __restrict__ al2, const float* __restrict__ ar2,
                        const float* __restrict__ W1, const float* __restrict__ W2,
                        const float* __restrict__ res_w, const int* __restrict__ dst,
                        float* __restrict__ d_out) {
    __shared__ float xs[64][68];
    __shared__ float ws[64][68];
    __shared__ float u1s[64][8];
    __shared__ float u2s[48];
    int b = blockIdx.x;
    int tid = threadIdx.x;
    if (b < GB) {  // ---- feat1 GEMM, x tile loaded once, loop over t ----
        int r0 = b * 64;
        for (int i = tid; i < 64 * 16; i += 256) {
            int r = i >> 4, c4 = (i & 15) << 2;
            float4 v = make_float4(0.f, 0.f, 0.f, 0.f);
            if (r0 + r < NN) v = *reinterpret_cast<const float4*>(x + (r0 + r) * 64 + c4);
            *reinterpret_cast<float4*>(&xs[r][c4]) = v;
        }
        int cc = (tid & 15) << 2;
        int rr = (tid >> 4) << 2;
        for (int t = 0; t < TT; t++) {
            __syncthreads();  // xs ready (t=0) / previous compute done before ws overwrite
            for (int i = tid; i < 64 * 16; i += 256) {
                int r = i >> 4, c4 = (i & 15) << 2;
                float4 w = *reinterpret_cast<const float4*>(W1 + (t * 64 + r) * 64 + c4);
                *reinterpret_cast<float4*>(&ws[r][c4]) = w;
            }
            __syncthreads();
            u64 acc2[4][2] = {};
            GEMM_CORE2(xs, ws, acc2, rr, cc)
#pragma unroll
            for (int i2 = 0; i2 < 4; i2++) {
                int r = r0 + rr + i2;
                if (r < NN) {
                    float2 lo = *reinterpret_cast<float2*>(&acc2[i2][0]);
                    float2 hi = *reinterpret_cast<float2*>(&acc2[i2][1]);
                    *reinterpret_cast<float4*>(&g_feat1[(r * TT + t) * 64 + cc]) =
                        make_float4(lo.x, lo.y, hi.x, hi.y);
                }
            }
        }
        return;
    }
    b -= GB;
    if (b < HIST_BLOCKS) {  // ---- dst histogram (hides under GEMM) ----
        int t0 = b * 1024 + tid;
#pragma unroll
        for (int k = 0; k < 4; k++) {
            int e = t0 + k * 256;
            if (e < EE) atomicAdd(&g_deg[dst[e]], 1);
        }
        return;
    }
    b -= HIST_BLOCKS;
    if (b < TT) {  // ---- v1 for type t ----
        int t = b;
        for (int e = tid; e < 512; e += 256) {
            int c = e >> 3, h = e & 7;
            const float* pl = al1 + t * 4096 + c * 64 + h * 8;
            const float* pr = ar1 + t * 4096 + c * 64 + h * 8;
            float s = 0.f;
#pragma unroll
            for (int d = 0; d < 8; d++) s += pl[d] + pr[d];
            u1s[c][h] = s;
        }
        __syncthreads();
        for (int e = tid; e < 512; e += 256) {
            int i = e >> 3, h = e & 7;
            const float* w = W1 + t * 4096 + i * 64;
            float s = 0.f;
#pragma unroll 8
            for (int c = 0; c < 64; c++) s = fmaf(w[c], u1s[c][h], s);
            g_v1[i * 24 + t * 8 + h] = s;
        }
        return;
    }
    b -= TT;
    if (b < 1) {  // ---- v2 + zero d_out ----
        if (tid < 48) {
            int t = tid >> 4, c = tid & 15;
            const float* pl = al2 + (t * 16 + c) * 16;
            const float* pr = ar2 + (t * 16 + c) * 16;
            float s = 0.f;
#pragma unroll
            for (int j = 0; j < 16; j++) s += pl[j] + pr[j];
            u2s[tid] = s;
        }
        if (tid >= 240 && tid < 240 + C2) d_out[tid - 240] = 0.f;
        __syncthreads();
        if (tid < 192) {
            int t = tid >> 6, i = tid & 63;
            const float* w = W2 + (t * 64 + i) * 16;
            float s = 0.f;
#pragma unroll
            for (int c = 0; c < 16; c++) s = fmaf(w[c], u2s[t * 16 + c], s);
            g_v2[tid] = s;
        }
        return;
    }
    b -= 1;
    if (b < 16) {  // ---- Wc ----
        int i = b * 256 + tid;
        int k = i >> 6, c = i & 63;
        float v;
        if (c < 48) v = W2[(((c >> 4) * D1) + k) * C2 + (c & 15)];
        else        v = res_w[k * C2 + (c - 48)];
        g_Wc[i] = v;
        return;
    }
}

// ---------------- Launch B: scan ----------------
__global__ void k_scan() {
    extern __shared__ int sdeg[];
    __shared__ int ss[1024];
    int tid = threadIdx.x;
    for (int i = tid; i < NN; i += 1024) sdeg[i] = g_deg[i];
    __syncthreads();
    const int CH = 49;
    int base = tid * CH;
    int s = 0;
    for (int i = 0; i < CH; i++) {
        int j = base + i;
        if (j < NN) s += sdeg[j];
    }
    ss[tid] = s;
    __syncthreads();
    for (int off = 1; off < 1024; off <<= 1) {
        int v = (tid >= off) ? ss[tid - off] : 0;
        __syncthreads();
        ss[tid] += v;
        __syncthreads();
    }
    if (tid == 1023) g_rowptr[NN] = ss[1023];
    int run = (tid > 0) ? ss[tid - 1] : 0;
    for (int i = 0; i < CH; i++) {
        int j = base + i;
        if (j < NN) {
            int d = sdeg[j];
            sdeg[j] = run;
            run += d;
        }
    }
    __syncthreads();
    for (int i = tid; i < NN; i += 1024) {
        int v = sdeg[i];
        g_rowptr[i] = v;
        g_cursor[i] = v;
    }
}

// ---------------- Launch C: scatter + es1 (es1 hides under scatter atomics) ----------------
__global__ void __launch_bounds__(256) k_scatter(const int* __restrict__ src,
                                                 const int* __restrict__ dst,
                                                 const int* __restrict__ etype,
                                                 const float* __restrict__ x) {
    __shared__ float xs[64][68];
    __shared__ float v1s[64][24];
    int b = blockIdx.x;
    int tid = threadIdx.x;
    if (b < HIST_BLOCKS) {  // ---- CSR scatter + re-zero deg ----
        int t0 = b * 1024 + tid;
#pragma unroll
        for (int k = 0; k < 4; k++) {
            int e = t0 + k * 256;
            if (e < EE) {
                int pos = atomicAdd(&g_cursor[dst[e]], 1);
                g_gather[pos] = src[e] * TT + etype[e];
            }
        }
        int gt = b * 256 + tid;
        for (int i = gt; i < NN; i += HIST_BLOCKS * 256) g_deg[i] = 0;
        return;
    }
    b -= HIST_BLOCKS;
    // ---- es1 tile: es1[n][t*8+h] = exp(leakyrelu( x[n,:] . v1[:, t*8+h] )) ----
    int r0 = b * 64;
    for (int i = tid; i < 64 * 16; i += 256) {
        int r = i >> 4, c4 = (i & 15) << 2;
        float4 v = make_float4(0.f, 0.f, 0.f, 0.f);
        if (r0 + r < NN) v = *reinterpret_cast<const float4*>(x + (r0 + r) * 64 + c4);
        *reinterpret_cast<float4*>(&xs[r][c4]) = v;
    }
    for (int i = tid; i < 64 * 24; i += 256) {
        int r = i / 24, c = i - r * 24;
        v1s[r][c] = g_v1[i];
    }
    __syncthreads();
    int row = tid >> 2;
    int c0 = (tid & 3) * 6;
    float s[6] = {0.f, 0.f, 0.f, 0.f, 0.f, 0.f};
#pragma unroll
    for (int i4 = 0; i4 < 64; i4 += 4) {
        float4 xv = *reinterpret_cast<const float4*>(&xs[row][i4]);
#pragma unroll
        for (int c = 0; c < 6; c++) {
            s[c] = fmaf(xv.x, v1s[i4][c0 + c], s[c]);
            s[c] = fmaf(xv.y, v1s[i4 + 1][c0 + c], s[c]);
            s[c] = fmaf(xv.z, v1s[i4 + 2][c0 + c], s[c]);
            s[c] = fmaf(xv.w, v1s[i4 + 3][c0 + c], s[c]);
        }
    }
    int n = r0 + row;
    if (n < NN) {
#pragma unroll
        for (int c = 0; c < 6; c++) {
            float a = s[c];
            a = a > 0.f ? a : 0.2f * a;
            g_es1[n * 24 + c0 + c] = expf(a);
        }
    }
}

// ---------------- Launch D: layer0 aggregation (warp/node) + fused es2 ----------------
__global__ void __launch_bounds__(256) k_agg1() {
    __shared__ float v2s[3][64];
    int tid = threadIdx.x;
    if (tid < 192) v2s[tid >> 6][tid & 63] = g_v2[tid];
    __syncthreads();
    int warp = tid >> 5, lane = tid & 31;
    int node = blockIdx.x * 8 + warp;
    if (node >= NN) return;
    int beg = g_rowptr[node], end = g_rowptr[node + 1];
    int j2 = lane * 2;
    int h = lane >> 2;
    float ax = 0.f, ay = 0.f, wsum = 0.f;
    int p = beg;
    for (; p + 4 <= end; p += 4) {
        int g0 = __ldg(&g_gather[p]);
        int g1 = __ldg(&g_gather[p + 1]);
        int g2 = __ldg(&g_gather[p + 2]);
        int g3 = __ldg(&g_gather[p + 3]);
        float w0 = __ldg(&g_es1[g0 * 8 + h]);
        float w1 = __ldg(&g_es1[g1 * 8 + h]);
        float w2 = __ldg(&g_es1[g2 * 8 + h]);
        float w3 = __ldg(&g_es1[g3 * 8 + h]);
        float2 f0 = __ldg(reinterpret_cast<const float2*>(&g_feat1[g0 * 64 + j2]));
        float2 f1 = __ldg(reinterpret_cast<const float2*>(&g_feat1[g1 * 64 + j2]));
        float2 f2 = __ldg(reinterpret_cast<const float2*>(&g_feat1[g2 * 64 + j2]));
        float2 f3 = __ldg(reinterpret_cast<const float2*>(&g_feat1[g3 * 64 + j2]));
        ax = fmaf(f0.x, w0, ax); ay = fmaf(f0.y, w0, ay);
        ax = fmaf(f1.x, w1, ax); ay = fmaf(f1.y, w1, ay);
        ax = fmaf(f2.x, w2, ax); ay = fmaf(f2.y, w2, ay);
        ax = fmaf(f3.x, w3, ax); ay = fmaf(f3.y, w3, ay);
        wsum += (w0 + w1) + (w2 + w3);
    }
    for (; p < end; p++) {
        int g = __ldg(&g_gather[p]);
        float w = __ldg(&g_es1[g * 8 + h]);
        float2 f = __ldg(reinterpret_cast<const float2*>(&g_feat1[g * 64 + j2]));
        ax = fmaf(f.x, w, ax); ay = fmaf(f.y, w, ay);
        wsum += w;
    }
    float vx = 0.f, vy = 0.f;
    if (end > beg) {
        vx = ax / wsum;
        vy = ay / wsum;
    }
    vx = vx > 0.f ? vx : (expf(vx) - 1.f);
    vy = vy > 0.f ? vy : (expf(vy) - 1.f);
    *reinterpret_cast<float2*>(&g_h[node * 64 + j2]) = make_float2(vx, vy);
    float p0 = vx * v2s[0][j2] + vy * v2s[0][j2 + 1];
    float p1 = vx * v2s[1][j2] + vy * v2s[1][j2 + 1];
    float p2 = vx * v2s[2][j2] + vy * v2s[2][j2 + 1];
#pragma unroll
    for (int off = 16; off > 0; off >>= 1) {
        p0 += __shfl_down_sync(0xffffffffu, p0, off);
        p1 += __shfl_down_sync(0xffffffffu, p1, off);
        p2 += __shfl_down_sync(0xffffffffu, p2, off);
    }
    if (lane == 0) {
        float s0 = p0 > 0.f ? p0 : 0.2f * p0;
        float s1 = p1 > 0.f ? p1 : 0.2f * p1;
        float s2 = p2 > 0.f ? p2 : 0.2f * p2;
        g_es2[node * 3 + 0] = expf(s0);
        g_es2[node * 3 + 1] = expf(s1);
        g_es2[node * 3 + 2] = expf(s2);
    }
}

// ---------------- Launch E: layer 1 GEMM: [feat2 | resid] = h @ Wc ----------------
__global__ void __launch_bounds__(256) k_feat2(const float* __restrict__ res_b) {
    __shared__ float xs[64][68];
    __shared__ float ws[64][68];
    int r0 = blockIdx.x * 64;
    int tid = threadIdx.x;
    for (int i = tid; i < 64 * 16; i += 256) {
        int r = i >> 4, c4 = (i & 15) << 2;
        float4 v = make_float4(0.f, 0.f, 0.f, 0.f);
        if (r0 + r < NN) v = *reinterpret_cast<const float4*>(g_h + (r0 + r) * 64 + c4);
        *reinterpret_cast<float4*>(&xs[r][c4]) = v;
        float4 w = *reinterpret_cast<const float4*>(g_Wc + r * 64 + c4);
        *reinterpret_cast<float4*>(&ws[r][c4]) = w;
    }
    __syncthreads();
    int cc = (tid & 15) << 2;
    int rr = (tid >> 4) << 2;
    u64 acc2[4][2] = {};
    GEMM_CORE2(xs, ws, acc2, rr, cc)
#pragma unroll
    for (int i2 = 0; i2 < 4; i2++) {
        int r = r0 + rr + i2;
        if (r < NN) {
            float2 lo = *reinterpret_cast<float2*>(&acc2[i2][0]);
            float2 hi = *reinterpret_cast<float2*>(&acc2[i2][1]);
            if (cc < 48) {
                int t = cc >> 4;
                *reinterpret_cast<float4*>(&g_feat2[(r * TT + t) * 16 + (cc & 15)]) =
                    make_float4(lo.x, lo.y, hi.x, hi.y);
            } else {
                int c0 = cc - 48;
                *reinterpret_cast<float4*>(&g_resid[r * 16 + c0]) =
                    make_float4(lo.x + res_b[c0], lo.y + res_b[c0 + 1],
                                hi.x + res_b[c0 + 2], hi.y + res_b[c0 + 3]);
            }
        }
    }
}

// ---------------- Launch F: layer1 aggregation + residual + mean pooling ----------------
__global__ void __launch_bounds__(256) k_agg2(float* __restrict__ d_out) {
    __shared__ float2 red[256];
    int tid = threadIdx.x;
    int grp = tid >> 3;
    int j = tid & 7;
    int node = blockIdx.x * 32 + grp;
    float2 val = make_float2(0.f, 0.f);
    if (node < NN) {
        int beg = g_rowptr[node], end = g_rowptr[node + 1];
        float ax = 0.f, ay = 0.f, wsum = 0.f;
        int p = beg;
        for (; p + 4 <= end; p += 4) {
            int g0 = __ldg(&g_gather[p]);
            int g1 = __ldg(&g_gather[p + 1]);
            int g2 = __ldg(&g_gather[p + 2]);
            int g3 = __ldg(&g_gather[p + 3]);
            float w0 = __ldg(&g_es2[g0]);
            float w1 = __ldg(&g_es2[g1]);
            float w2 = __ldg(&g_es2[g2]);
            float w3 = __ldg(&g_es2[g3]);
            float2 f0 = __ldg(reinterpret_cast<const float2*>(&g_feat2[g0 * 16 + j * 2]));
            float2 f1 = __ldg(reinterpret_cast<const float2*>(&g_feat2[g1 * 16 + j * 2]));
            float2 f2 = __ldg(reinterpret_cast<const float2*>(&g_feat2[g2 * 16 + j * 2]));
            float2 f3 = __ldg(reinterpret_cast<const float2*>(&g_feat2[g3 * 16 + j * 2]));
            ax = fmaf(f0.x, w0, ax); ay = fmaf(f0.y, w0, ay);
            ax = fmaf(f1.x, w1, ax); ay = fmaf(f1.y, w1, ay);
            ax = fmaf(f2.x, w2, ax); ay = fmaf(f2.y, w2, ay);
            ax = fmaf(f3.x, w3, ax); ay = fmaf(f3.y, w3, ay);
            wsum += (w0 + w1) + (w2 + w3);
        }
        for (; p < end; p++) {
            int g = __ldg(&g_gather[p]);
            float w = __ldg(&g_es2[g]);
            float2 f = __ldg(reinterpret_cast<const float2*>(&g_feat2[g * 16 + j * 2]));
            ax = fmaf(f.x, w, ax); ay = fmaf(f.y, w, ay);
            wsum += w;
        }
        float2 rs = *reinterpret_cast<const float2*>(&g_resid[node * 16 + j * 2]);
        val.x = ((end > beg) ? ax / wsum : 0.f) + rs.x;
        val.y = ((end > beg) ? ay / wsum : 0.f) + rs.y;
    }
    val.x *= (1.0f / NN);
    val.y *= (1.0f / NN);
    red[tid] = val;
    __syncthreads();
#pragma unroll
    for (int s = 16; s > 0; s >>= 1) {
        if (grp < s) {
            float2 o = red[tid + s * 8];
            red[tid].x += o.x;
            red[tid].y += o.y;
        }
        __syncthreads();
    }
    if (tid < 8) {
        atomicAdd(&d_out[tid * 2], red[tid].x);
        atomicAdd(&d_out[tid * 2 + 1], red[tid].y);
    }
}

// ---------------- launch ----------------
extern "C" void kernel_launch(void* const* d_in, const int* in_sizes, int n_in,
                              void* d_out, int out_size) {
    const float* x     = (const float*)d_in[0];
    const int*   src   = (const int*)d_in[1];
    const int*   dst   = (const int*)d_in[2];
    const int*   etype = (const int*)d_in[4];
    const float* W1    = (const float*)d_in[5];
    const float* al1   = (const float*)d_in[6];
    const float* ar1   = (const float*)d_in[7];
    const float* W2    = (const float*)d_in[8];
    const float* al2   = (const float*)d_in[9];
    const float* ar2   = (const float*)d_in[10];
    const float* res_w = (const float*)d_in[11];
    const float* res_b = (const float*)d_in[12];
    float* out = (float*)d_out;

    cudaFuncSetAttribute(k_scan, cudaFuncAttributeMaxDynamicSharedMemorySize, NN * 4);

    k_setup<<<GB + HIST_BLOCKS + TT + 1 + 16, 256>>>(x, al1, ar1, al2, ar2, W1, W2,
                                                     res_w, dst, out);
    k_scan<<<1, 1024, NN * 4>>>();
    k_scatter<<<HIST_BLOCKS + GB, 256>>>(src, dst, etype, x);
    k_agg1<<<(NN + 7) / 8, 256>>>();
    k_feat2<<<(NN + 63) / 64, 256>>>(res_b);
    k_agg2<<<(NN + 31) / 32, 256>>>(out);
}

// round 15
// speedup vs baseline: 1.4116x; 1.0346x over previous
#include <cuda_runtime.h>
#include <cuda_fp16.h>

#define NN 50000
#define EE 800000
#define TT 3
#define HH 8
#define D1 64
#define C2 16

typedef unsigned long long u64;

struct alignas(8) h4 { __half2 a, b; };

// ---------------- scratch (static device globals; no allocation) ----------------
__device__ __half g_feat1h[NN * TT * D1]; // 19.2 MB (fp16 feature payload)
__device__ float g_es1[NN * TT * HH];     // 4.8 MB  [n][t][h]
__device__ float g_h[NN * D1];            // 12.8 MB
__device__ __half g_feat2h[NN * TT * C2]; // 4.8 MB
__device__ float g_es2[NN * TT];          // 0.6 MB
__device__ float g_resid[NN * C2];        // 3.2 MB
__device__ float g_v1[D1 * TT * HH];
__device__ float g_v2[TT * D1];
__device__ float g_Wc[D1 * 64];
__device__ int   g_deg[NN];
__device__ int   g_rowptr[NN + 1];
__device__ int   g_cursor[NN];
__device__ int   g_gather[EE];

#define HIST_BLOCKS ((EE + 1023) / 1024)   // 782
#define GB ((NN + 63) / 64)                // 782 (== HIST_BLOCKS: parity-interleave)

// ---------------- f32x2 packed-FMA helpers ----------------
__device__ __forceinline__ u64 pack2(float v) {
    u64 r;
    unsigned u = __float_as_uint(v);
    asm("mov.b64 %0, {%1, %1};" : "=l"(r) : "r"(u));
    return r;
}
__device__ __forceinline__ void ffma2(u64& d, u64 a, u64 b) {
    asm("fma.rn.f32x2 %0, %1, %2, %0;" : "+l"(d) : "l"(a), "l"(b));
}

#define GEMM_ROW(ACCR, AV, B0, B1, B2, B3) {                                        \
        u64 t_;                                                                     \
        t_ = pack2(AV.x); ffma2(ACCR[0], t_, B0.x); ffma2(ACCR[1], t_, B0.y);       \
        t_ = pack2(AV.y); ffma2(ACCR[0], t_, B1.x); ffma2(ACCR[1], t_, B1.y);       \
        t_ = pack2(AV.z); ffma2(ACCR[0], t_, B2.x); ffma2(ACCR[1], t_, B2.y);       \
        t_ = pack2(AV.w); ffma2(ACCR[0], t_, B3.x); ffma2(ACCR[1], t_, B3.y);       \
    }

#define GEMM_CORE2(XS, WS, ACC2, RR, CC)                                            \
    _Pragma("unroll")                                                               \
    for (int k4 = 0; k4 < 64; k4 += 4) {                                            \
        float4 a0 = *reinterpret_cast<const float4*>(&XS[RR][k4]);                  \
        float4 a1 = *reinterpret_cast<const float4*>(&XS[RR + 1][k4]);              \
        float4 a2 = *reinterpret_cast<const float4*>(&XS[RR + 2][k4]);              \
        float4 a3 = *reinterpret_cast<const float4*>(&XS[RR + 3][k4]);              \
        ulonglong2 b0 = *reinterpret_cast<const ulonglong2*>(&WS[k4][CC]);          \
        ulonglong2 b1 = *reinterpret_cast<const ulonglong2*>(&WS[k4 + 1][CC]);      \
        ulonglong2 b2 = *reinterpret_cast<const ulonglong2*>(&WS[k4 + 2][CC]);      \
        ulonglong2 b3 = *reinterpret_cast<const ulonglong2*>(&WS[k4 + 3][CC]);      \
        GEMM_ROW(ACC2[0], a0, b0, b1, b2, b3)                                       \
        GEMM_ROW(ACC2[1], a1, b0, b1, b2, b3)                                       \
        GEMM_ROW(ACC2[2], a2, b0, b1, b2, b3)                                       \
        GEMM_ROW(ACC2[3], a3, b0, b1, b2, b3)                                       \
    }

// ---------------- Launch A: feat1 GEMM + hist (parity-interleaved) + v1/v2/Wc ----------------
__global__ void __launch_bounds__(256) k_setup(const float* __restrict__ x,
                        const float* __restrict__ al1, const float* __restrict__ ar1,
                        const float* __restrict__ al2, const float* __restrict__ ar2,
                        const float* __restrict__ W1, const float* __restrict__ W2,
                        const float* __restrict__ res_w, const int* __restrict__ dst,
                        float* __restrict__ d_out) {
    __shared__ float xs[64][68];
    __shared__ float ws[64][68];
    __shared__ float u1s[64][8];
    __shared__ float u2s[48];
    int b = blockIdx.x;
    int tid = threadIdx.x;
    if (b < 2 * GB) {
        if (b & 1) {  // ---- dst histogram (odd bids: co-resident with GEMM) ----
            int hb = b >> 1;
            int t0 = hb * 1024 + tid;
#pragma unroll
            for (int k = 0; k < 4; k++) {
                int e = t0 + k * 256;
                if (e < EE) atomicAdd(&g_deg[dst[e]], 1);
            }
            return;
        }
        // ---- feat1 GEMM (even bids), x tile loaded once, loop over t ----
        int gb = b >> 1;
        int r0 = gb * 64;
        for (int i = tid; i < 64 * 16; i += 256) {
            int r = i >> 4, c4 = (i & 15) << 2;
            float4 v = make_float4(0.f, 0.f, 0.f, 0.f);
            if (r0 + r < NN) v = *reinterpret_cast<const float4*>(x + (r0 + r) * 64 + c4);
            *reinterpret_cast<float4*>(&xs[r][c4]) = v;
        }
        int cc = (tid & 15) << 2;
        int rr = (tid >> 4) << 2;
        for (int t = 0; t < TT; t++) {
            __syncthreads();
            for (int i = tid; i < 64 * 16; i += 256) {
                int r = i >> 4, c4 = (i & 15) << 2;
                float4 w = *reinterpret_cast<const float4*>(W1 + (t * 64 + r) * 64 + c4);
                *reinterpret_cast<float4*>(&ws[r][c4]) = w;
            }
            __syncthreads();
            u64 acc2[4][2] = {};
            GEMM_CORE2(xs, ws, acc2, rr, cc)
#pragma unroll
            for (int i2 = 0; i2 < 4; i2++) {
                int r = r0 + rr + i2;
                if (r < NN) {
                    float2 lo = *reinterpret_cast<float2*>(&acc2[i2][0]);
                    float2 hi = *reinterpret_cast<float2*>(&acc2[i2][1]);
                    h4 o;
                    o.a = __floats2half2_rn(lo.x, lo.y);
                    o.b = __floats2half2_rn(hi.x, hi.y);
                    *reinterpret_cast<h4*>(&g_feat1h[(r * TT + t) * 64 + cc]) = o;
                }
            }
        }
        return;
    }
    b -= 2 * GB;
    if (b < TT) {  // ---- v1 for type t ----
        int t = b;
        for (int e = tid; e < 512; e += 256) {
            int c = e >> 3, h = e & 7;
            const float* pl = al1 + t * 4096 + c * 64 + h * 8;
            const float* pr = ar1 + t * 4096 + c * 64 + h * 8;
            float s = 0.f;
#pragma unroll
            for (int d = 0; d < 8; d++) s += pl[d] + pr[d];
            u1s[c][h] = s;
        }
        __syncthreads();
        for (int e = tid; e < 512; e += 256) {
            int i = e >> 3, h = e & 7;
            const float* w = W1 + t * 4096 + i * 64;
            float s = 0.f;
#pragma unroll 8
            for (int c = 0; c < 64; c++) s = fmaf(w[c], u1s[c][h], s);
            g_v1[i * 24 + t * 8 + h] = s;
        }
        return;
    }
    b -= TT;
    if (b < 1) {  // ---- v2 + zero d_out ----
        if (tid < 48) {
            int t = tid >> 4, c = tid & 15;
            const float* pl = al2 + (t * 16 + c) * 16;
            const float* pr = ar2 + (t * 16 + c) * 16;
            float s = 0.f;
#pragma unroll
            for (int j = 0; j < 16; j++) s += pl[j] + pr[j];
            u2s[tid] = s;
        }
        if (tid >= 240 && tid < 240 + C2) d_out[tid - 240] = 0.f;
        __syncthreads();
        if (tid < 192) {
            int t = tid >> 6, i = tid & 63;
            const float* w = W2 + (t * 64 + i) * 16;
            float s = 0.f;
#pragma unroll
            for (int c = 0; c < 16; c++) s = fmaf(w[c], u2s[t * 16 + c], s);
            g_v2[tid] = s;
        }
        return;
    }
    b -= 1;
    if (b < 16) {  // ---- Wc ----
        int i = b * 256 + tid;
        int k = i >> 6, c = i & 63;
        float v;
        if (c < 48) v = W2[(((c >> 4) * D1) + k) * C2 + (c & 15)];
        else        v = res_w[k * C2 + (c - 48)];
        g_Wc[i] = v;
        return;
    }
}

// ---------------- Launch B: scan ----------------
__global__ void k_scan() {
    extern __shared__ int sdeg[];
    __shared__ int ss[1024];
    int tid = threadIdx.x;
    for (int i = tid; i < NN; i += 1024) sdeg[i] = g_deg[i];
    __syncthreads();
    const int CH = 49;
    int base = tid * CH;
    int s = 0;
    for (int i = 0; i < CH; i++) {
        int j = base + i;
        if (j < NN) s += sdeg[j];
    }
    ss[tid] = s;
    __syncthreads();
    for (int off = 1; off < 1024; off <<= 1) {
        int v = (tid >= off) ? ss[tid - off] : 0;
        __syncthreads();
        ss[tid] += v;
        __syncthreads();
    }
    if (tid == 1023) g_rowptr[NN] = ss[1023];
    int run = (tid > 0) ? ss[tid - 1] : 0;
    for (int i = 0; i < CH; i++) {
        int j = base + i;
        if (j < NN) {
            int d = sdeg[j];
            sdeg[j] = run;
            run += d;
        }
    }
    __syncthreads();
    for (int i = tid; i < NN; i += 1024) {
        int v = sdeg[i];
        g_rowptr[i] = v;
        g_cursor[i] = v;
    }
}

// ---------------- Launch C: scatter + es1 (parity-interleaved) ----------------
__global__ void __launch_bounds__(256) k_scatter(const int* __restrict__ src,
                                                 const int* __restrict__ dst,
                                                 const int* __restrict__ etype,
                                                 const float* __restrict__ x) {
    __shared__ float xs[64][68];
    __shared__ float v1s[64][24];
    int b = blockIdx.x;
    int tid = threadIdx.x;
    if (b < 2 * HIST_BLOCKS) {
        if (b & 1) {  // ---- CSR scatter (odd) + re-zero deg ----
            int sb = b >> 1;
            int t0 = sb * 1024 + tid;
#pragma unroll
            for (int k = 0; k < 4; k++) {
                int e = t0 + k * 256;
                if (e < EE) {
                    int pos = atomicAdd(&g_cursor[dst[e]], 1);
                    g_gather[pos] = src[e] * TT + etype[e];
                }
            }
            int gt = sb * 256 + tid;
            for (int i = gt; i < NN; i += HIST_BLOCKS * 256) g_deg[i] = 0;
            return;
        }
        // ---- es1 tile (even): es1[n][t*8+h] = exp(leakyrelu( x[n,:] . v1[:, t*8+h] )) ----
        int eb = b >> 1;
        int r0 = eb * 64;
        for (int i = tid; i < 64 * 16; i += 256) {
            int r = i >> 4, c4 = (i & 15) << 2;
            float4 v = make_float4(0.f, 0.f, 0.f, 0.f);
            if (r0 + r < NN) v = *reinterpret_cast<const float4*>(x + (r0 + r) * 64 + c4);
            *reinterpret_cast<float4*>(&xs[r][c4]) = v;
        }
        for (int i = tid; i < 64 * 24; i += 256) {
            int r = i / 24, c = i - r * 24;
            v1s[r][c] = g_v1[i];
        }
        __syncthreads();
        int row = tid >> 2;
        int c0 = (tid & 3) * 6;
        float s[6] = {0.f, 0.f, 0.f, 0.f, 0.f, 0.f};
#pragma unroll
        for (int i4 = 0; i4 < 64; i4 += 4) {
            float4 xv = *reinterpret_cast<const float4*>(&xs[row][i4]);
#pragma unroll
            for (int c = 0; c < 6; c++) {
                s[c] = fmaf(xv.x, v1s[i4][c0 + c], s[c]);
                s[c] = fmaf(xv.y, v1s[i4 + 1][c0 + c], s[c]);
                s[c] = fmaf(xv.z, v1s[i4 + 2][c0 + c], s[c]);
                s[c] = fmaf(xv.w, v1s[i4 + 3][c0 + c], s[c]);
            }
        }
        int n = r0 + row;
        if (n < NN) {
#pragma unroll
            for (int c = 0; c < 6; c++) {
                float a = s[c];
                a = a > 0.f ? a : 0.2f * a;
                g_es1[n * 24 + c0 + c] = expf(a);
            }
        }
    }
}

// ---------------- Launch D: layer0 aggregation (warp/node, fp16 feat) + fused es2 ----------------
__global__ void __launch_bounds__(256) k_agg1() {
    __shared__ float v2s[3][64];
    int tid = threadIdx.x;
    if (tid < 192) v2s[tid >> 6][tid & 63] = g_v2[tid];
    __syncthreads();
    int warp = tid >> 5, lane = tid & 31;
    int node = blockIdx.x * 8 + warp;
    if (node >= NN) return;
    int beg = g_rowptr[node], end = g_rowptr[node + 1];
    int j2 = lane * 2;
    int h = lane >> 2;
    float ax = 0.f, ay = 0.f, wsum = 0.f;
    int p = beg;
    for (; p + 4 <= end; p += 4) {
        int g0 = __ldg(&g_gather[p]);
        int g1 = __ldg(&g_gather[p + 1]);
        int g2 = __ldg(&g_gather[p + 2]);
        int g3 = __ldg(&g_gather[p + 3]);
        float w0 = __ldg(&g_es1[g0 * 8 + h]);
        float w1 = __ldg(&g_es1[g1 * 8 + h]);
        float w2 = __ldg(&g_es1[g2 * 8 + h]);
        float w3 = __ldg(&g_es1[g3 * 8 + h]);
        float2 f0 = __half22float2(__ldg(reinterpret_cast<const __half2*>(&g_feat1h[g0 * 64 + j2])));
        float2 f1 = __half22float2(__ldg(reinterpret_cast<const __half2*>(&g_feat1h[g1 * 64 + j2])));
        float2 f2 = __half22float2(__ldg(reinterpret_cast<const __half2*>(&g_feat1h[g2 * 64 + j2])));
        float2 f3 = __half22float2(__ldg(reinterpret_cast<const __half2*>(&g_feat1h[g3 * 64 + j2])));
        ax = fmaf(f0.x, w0, ax); ay = fmaf(f0.y, w0, ay);
        ax = fmaf(f1.x, w1, ax); ay = fmaf(f1.y, w1, ay);
        ax = fmaf(f2.x, w2, ax); ay = fmaf(f2.y, w2, ay);
        ax = fmaf(f3.x, w3, ax); ay = fmaf(f3.y, w3, ay);
        wsum += (w0 + w1) + (w2 + w3);
    }
    for (; p < end; p++) {
        int g = __ldg(&g_gather[p]);
        float w = __ldg(&g_es1[g * 8 + h]);
        float2 f = __half22float2(__ldg(reinterpret_cast<const __half2*>(&g_feat1h[g * 64 + j2])));
        ax = fmaf(f.x, w, ax); ay = fmaf(f.y, w, ay);
        wsum += w;
    }
    float vx = 0.f, vy = 0.f;
    if (end > beg) {
        vx = ax / wsum;
        vy = ay / wsum;
    }
    vx = vx > 0.f ? vx : (expf(vx) - 1.f);
    vy = vy > 0.f ? vy : (expf(vy) - 1.f);
    *reinterpret_cast<float2*>(&g_h[node * 64 + j2]) = make_float2(vx, vy);
    float p0 = vx * v2s[0][j2] + vy * v2s[0][j2 + 1];
    float p1 = vx * v2s[1][j2] + vy * v2s[1][j2 + 1];
    float p2 = vx * v2s[2][j2] + vy * v2s[2][j2 + 1];
#pragma unroll
    for (int off = 16; off > 0; off >>= 1) {
        p0 += __shfl_down_sync(0xffffffffu, p0, off);
        p1 += __shfl_down_sync(0xffffffffu, p1, off);
        p2 += __shfl_down_sync(0xffffffffu, p2, off);
    }
    if (lane == 0) {
        float s0 = p0 > 0.f ? p0 : 0.2f * p0;
        float s1 = p1 > 0.f ? p1 : 0.2f * p1;
        float s2 = p2 > 0.f ? p2 : 0.2f * p2;
        g_es2[node * 3 + 0] = expf(s0);
        g_es2[node * 3 + 1] = expf(s1);
        g_es2[node * 3 + 2] = expf(s2);
    }
}

// ---------------- Launch E: layer 1 GEMM: [feat2(fp16) | resid(fp32)] = h @ Wc ----------------
__global__ void __launch_bounds__(256) k_feat2(const float* __restrict__ res_b) {
    __shared__ float xs[64][68];
    __shared__ float ws[64][68];
    int r0 = blockIdx.x * 64;
    int tid = threadIdx.x;
    for (int i = tid; i < 64 * 16; i += 256) {
        int r = i >> 4, c4 = (i & 15) << 2;
        float4 v = make_float4(0.f, 0.f, 0.f, 0.f);
        if (r0 + r < NN) v = *reinterpret_cast<const float4*>(g_h + (r0 + r) * 64 + c4);
        *reinterpret_cast<float4*>(&xs[r][c4]) = v;
        float4 w = *reinterpret_cast<const float4*>(g_Wc + r * 64 + c4);
        *reinterpret_cast<float4*>(&ws[r][c4]) = w;
    }
    __syncthreads();
    int cc = (tid & 15) << 2;
    int rr = (tid >> 4) << 2;
    u64 acc2[4][2] = {};
    GEMM_CORE2(xs, ws, acc2, rr, cc)
#pragma unroll
    for (int i2 = 0; i2 < 4; i2++) {
        int r = r0 + rr + i2;
        if (r < NN) {
            float2 lo = *reinterpret_cast<float2*>(&acc2[i2][0]);
            float2 hi = *reinterpret_cast<float2*>(&acc2[i2][1]);
            if (cc < 48) {
                int t = cc >> 4;
                h4 o;
                o.a = __floats2half2_rn(lo.x, lo.y);
                o.b = __floats2half2_rn(hi.x, hi.y);
                *reinterpret_cast<h4*>(&g_feat2h[(r * TT + t) * 16 + (cc & 15)]) = o;
            } else {
                int c0 = cc - 48;
                *reinterpret_cast<float4*>(&g_resid[r * 16 + c0]) =
                    make_float4(lo.x + res_b[c0], lo.y + res_b[c0 + 1],
                                hi.x + res_b[c0 + 2], hi.y + res_b[c0 + 3]);
            }
        }
    }
}

// ---------------- Launch F: layer1 aggregation (fp16 feat) + residual + mean pooling ----------------
__global__ void __launch_bounds__(256) k_agg2(float* __restrict__ d_out) {
    __shared__ float2 red[256];
    int tid = threadIdx.x;
    int grp = tid >> 3;
    int j = tid & 7;
    int node = blockIdx.x * 32 + grp;
    float2 val = make_float2(0.f, 0.f);
    if (node < NN) {
        int beg = g_rowptr[node], end = g_rowptr[node + 1];
        float ax = 0.f, ay = 0.f, wsum = 0.f;
        int p = beg;
        for (; p + 4 <= end; p += 4) {
            int g0 = __ldg(&g_gather[p]);
            int g1 = __ldg(&g_gather[p + 1]);
            int g2 = __ldg(&g_gather[p + 2]);
            int g3 = __ldg(&g_gather[p + 3]);
            float w0 = __ldg(&g_es2[g0]);
            float w1 = __ldg(&g_es2[g1]);
            float w2 = __ldg(&g_es2[g2]);
            float w3 = __ldg(&g_es2[g3]);
            float2 f0 = __half22float2(__ldg(reinterpret_cast<const __half2*>(&g_feat2h[g0 * 16 + j * 2])));
            float2 f1 = __half22float2(__ldg(reinterpret_cast<const __half2*>(&g_feat2h[g1 * 16 + j * 2])));
            float2 f2 = __half22float2(__ldg(reinterpret_cast<const __half2*>(&g_feat2h[g2 * 16 + j * 2])));
            float2 f3 = __half22float2(__ldg(reinterpret_cast<const __half2*>(&g_feat2h[g3 * 16 + j * 2])));
            ax = fmaf(f0.x, w0, ax); ay = fmaf(f0.y, w0, ay);
            ax = fmaf(f1.x, w1, ax); ay = fmaf(f1.y, w1, ay);
            ax = fmaf(f2.x, w2, ax); ay = fmaf(f2.y, w2, ay);
            ax = fmaf(f3.x, w3, ax); ay = fmaf(f3.y, w3, ay);
            wsum += (w0 + w1) + (w2 + w3);
        }
        for (; p < end; p++) {
            int g = __ldg(&g_gather[p]);
            float w = __ldg(&g_es2[g]);
            float2 f = __half22float2(__ldg(reinterpret_cast<const __half2*>(&g_feat2h[g * 16 + j * 2])));
            ax = fmaf(f.x, w, ax); ay = fmaf(f.y, w, ay);
            wsum += w;
        }
        float2 rs = *reinterpret_cast<const float2*>(&g_resid[node * 16 + j * 2]);
        val.x = ((end > beg) ? ax / wsum : 0.f) + rs.x;
        val.y = ((end > beg) ? ay / wsum : 0.f) + rs.y;
    }
    val.x *= (1.0f / NN);
    val.y *= (1.0f / NN);
    red[tid] = val;
    __syncthreads();
#pragma unroll
    for (int s = 16; s > 0; s >>= 1) {
        if (grp < s) {
            float2 o = red[tid + s * 8];
            red[tid].x += o.x;
            red[tid].y += o.y;
        }
        __syncthreads();
    }
    if (tid < 8) {
        atomicAdd(&d_out[tid * 2], red[tid].x);
        atomicAdd(&d_out[tid * 2 + 1], red[tid].y);
    }
}

// ---------------- launch ----------------
extern "C" void kernel_launch(void* const* d_in, const int* in_sizes, int n_in,
                              void* d_out, int out_size) {
    const float* x     = (const float*)d_in[0];
    const int*   src   = (const int*)d_in[1];
    const int*   dst   = (const int*)d_in[2];
    const int*   etype = (const int*)d_in[4];
    const float* W1    = (const float*)d_in[5];
    const float* al1   = (const float*)d_in[6];
    const float* ar1   = (const float*)d_in[7];
    const float* W2    = (const float*)d_in[8];
    const float* al2   = (const float*)d_in[9];
    const float* ar2   = (const float*)d_in[10];
    const float* res_w = (const float*)d_in[11];
    const float* res_b = (const float*)d_in[12];
    float* out = (float*)d_out;

    cudaFuncSetAttribute(k_scan, cudaFuncAttributeMaxDynamicSharedMemorySize, NN * 4);

    k_setup<<<2 * GB + TT + 1 + 16, 256>>>(x, al1, ar1, al2, ar2, W1, W2, res_w, dst, out);
    k_scan<<<1, 1024, NN * 4>>>();
    k_scatter<<<2 * HIST_BLOCKS, 256>>>(src, dst, etype, x);
    k_agg1<<<(NN + 7) / 8, 256>>>();
    k_feat2<<<(NN + 63) / 64, 256>>>(res_b);
    k_agg2<<<(NN + 31) / 32, 256>>>(out);
}